// round 1
// baseline (speedup 1.0000x reference)
#include <cuda_runtime.h>
#include <math.h>

#define TT 128
#define BB 1024
#define HH 256
#define G4 (4*HH)          // 1024
#define TB (TT*BB)         // 131072

// ---------------- scratch (allocation-free: __device__ globals) ----------------
__device__ float g_bufA[TB*HH];          // 134 MB
__device__ float g_bufB[TB*HH];          // 134 MB
__device__ float g_bufC[TB*HH];          // 134 MB
__device__ float g_A0[TB*G4];            // 537 MB : precomputed u@Wih0^T + biases
__device__ float g_state[4*BB*HH];       // h0,c0,h1,c1
__device__ float g_gates[2*BB*G4];       // gates0, gates1

// ---------------- zero the recurrent state ----------------
__global__ void zero_state(float* s) {
    int idx = blockIdx.x * blockDim.x + threadIdx.x;
    s[idx] = 0.f;
}

// ---------------- input MLP layer 1: [TB,6] -> relu -> [TB,256] ----------------
__global__ void in_mlp1(const float* __restrict__ x, const float* __restrict__ W,
                        const float* __restrict__ b, float* __restrict__ out) {
    int idx = blockIdx.x * blockDim.x + threadIdx.x;   // < TB*HH
    int m = idx >> 8;
    int n = idx & 255;
    const float* xr = x + m * 6;
    const float* wr = W + n * 6;
    float s = b[n];
#pragma unroll
    for (int k = 0; k < 6; k++) s = fmaf(xr[k], wr[k], s);
    out[idx] = fmaxf(s, 0.f);
}

// ---------------- generic tiled SGEMM: C = act(A@B^T [+ A2@B2^T] + bias [+ Cinit]) ----
// A:[M,K] row-major, B:[N,K] row-major. 64x64x16 tiles, 256 threads, 4x4/thread.
__global__ __launch_bounds__(256) void sgemm(
    int M, int N, int K,
    const float* __restrict__ A,  const float* __restrict__ B,
    const float* __restrict__ A2, const float* __restrict__ B2,
    const float* __restrict__ bias1, const float* __restrict__ bias2,
    const float* __restrict__ Cinit,
    float* __restrict__ C, int do_relu)
{
    __shared__ float As[16][68];
    __shared__ float Bs[16][68];
    int tid = threadIdx.x;
    int tx = tid & 15, ty = tid >> 4;
    int row0 = blockIdx.y << 6, col0 = blockIdx.x << 6;
    int lm = tid >> 2;            // 0..63 tile row
    int lk = (tid & 3) << 2;      // 0,4,8,12 k offset

    float acc[4][4] = {};

    int npass = A2 ? 2 : 1;
    for (int pass = 0; pass < npass; pass++) {
        const float* Ap = pass ? A2 : A;
        const float* Bp = pass ? B2 : B;
        const float* Arow = Ap + (size_t)(row0 + lm) * K + lk;
        const float* Brow = Bp + (size_t)(col0 + lm) * K + lk;
        for (int k0 = 0; k0 < K; k0 += 16) {
            float4 av = *(const float4*)(Arow + k0);
            float4 bv = *(const float4*)(Brow + k0);
            __syncthreads();
            As[lk+0][lm] = av.x; As[lk+1][lm] = av.y;
            As[lk+2][lm] = av.z; As[lk+3][lm] = av.w;
            Bs[lk+0][lm] = bv.x; Bs[lk+1][lm] = bv.y;
            Bs[lk+2][lm] = bv.z; Bs[lk+3][lm] = bv.w;
            __syncthreads();
#pragma unroll
            for (int k = 0; k < 16; k++) {
                float4 a = *(const float4*)&As[k][ty << 2];
                float4 b = *(const float4*)&Bs[k][tx << 2];
                float ar[4] = {a.x, a.y, a.z, a.w};
                float br[4] = {b.x, b.y, b.z, b.w};
#pragma unroll
                for (int i = 0; i < 4; i++)
#pragma unroll
                    for (int j = 0; j < 4; j++)
                        acc[i][j] = fmaf(ar[i], br[j], acc[i][j]);
            }
        }
    }

    float badd[4];
#pragma unroll
    for (int j = 0; j < 4; j++) {
        int c = col0 + (tx << 2) + j;
        float v = bias1 ? bias1[c] : 0.f;
        if (bias2) v += bias2[c];
        badd[j] = v;
    }
#pragma unroll
    for (int i = 0; i < 4; i++) {
        int r = row0 + (ty << 2) + i;
        size_t off = (size_t)r * N + col0 + (tx << 2);
#pragma unroll
        for (int j = 0; j < 4; j++) {
            float v = acc[i][j] + badd[j];
            if (Cinit) v += Cinit[off + j];
            if (do_relu) v = fmaxf(v, 0.f);
            C[off + j] = v;
        }
    }
}

// ---------------- LSTM cell elementwise (PyTorch gate order i,f,g,o) ----------------
__global__ void lstm_cell(const float* __restrict__ gates,
                          float* __restrict__ c, float* __restrict__ h,
                          float* __restrict__ hs /* nullable: stores relu(h) */) {
    int idx = blockIdx.x * blockDim.x + threadIdx.x;   // < BB*HH
    int b = idx >> 8, j = idx & 255;
    const float* g = gates + b * G4 + j;
    float gi = g[0], gf = g[HH], gg = g[2*HH], go = g[3*HH];
    float si = 1.f / (1.f + expf(-gi));
    float sf = 1.f / (1.f + expf(-gf));
    float so = 1.f / (1.f + expf(-go));
    float c2 = sf * c[idx] + si * tanhf(gg);
    float h2 = so * tanhf(c2);
    c[idx] = c2;
    h[idx] = h2;
    if (hs) hs[idx] = fmaxf(h2, 0.f);
}

// ---------------- output MLP final layer: [TB,256] -> [TB,6] ----------------
__global__ void out_mlp(const float* __restrict__ Y, const float* __restrict__ W,
                        const float* __restrict__ b, float* __restrict__ out) {
    int idx = blockIdx.x * blockDim.x + threadIdx.x;
    if (idx >= TB * 6) return;
    int m = idx / 6, n = idx % 6;
    const float* yr = Y + (size_t)m * HH;
    const float* wr = W + n * HH;
    float s = b[n];
#pragma unroll 8
    for (int k = 0; k < HH; k++) s = fmaf(yr[k], wr[k], s);
    out[idx] = s;
}

// ---------------- launch ----------------
extern "C" void kernel_launch(void* const* d_in, const int* in_sizes, int n_in,
                              void* d_out, int out_size) {
    const float* x    = (const float*)d_in[0];
    const float* Wi1  = (const float*)d_in[1];
    const float* bi1  = (const float*)d_in[2];
    const float* Wi2  = (const float*)d_in[3];
    const float* bi2  = (const float*)d_in[4];
    const float* Wi3  = (const float*)d_in[5];
    const float* bi3  = (const float*)d_in[6];
    const float* Wih0 = (const float*)d_in[7];
    const float* Whh0 = (const float*)d_in[8];
    const float* bih0 = (const float*)d_in[9];
    const float* bhh0 = (const float*)d_in[10];
    const float* Wih1 = (const float*)d_in[11];
    const float* Whh1 = (const float*)d_in[12];
    const float* bih1 = (const float*)d_in[13];
    const float* bhh1 = (const float*)d_in[14];
    const float* Wo1  = (const float*)d_in[15];
    const float* bo1  = (const float*)d_in[16];
    const float* Wo2  = (const float*)d_in[17];
    const float* bo2  = (const float*)d_in[18];
    const float* Wo3  = (const float*)d_in[19];
    const float* bo3  = (const float*)d_in[20];
    float* out = (float*)d_out;

    float *bufA, *bufB, *bufC, *A0, *state, *gates;
    cudaGetSymbolAddress((void**)&bufA, g_bufA);
    cudaGetSymbolAddress((void**)&bufB, g_bufB);
    cudaGetSymbolAddress((void**)&bufC, g_bufC);
    cudaGetSymbolAddress((void**)&A0, g_A0);
    cudaGetSymbolAddress((void**)&state, g_state);
    cudaGetSymbolAddress((void**)&gates, g_gates);

    float* h0 = state;
    float* c0 = state + BB * HH;
    float* h1 = state + 2 * BB * HH;
    float* c1 = state + 3 * BB * HH;
    float* gates0 = gates;
    float* gates1 = gates + BB * G4;

    // ---- parallel phase: input MLP + precompute A0 = u @ Wih0^T + (bih0+bhh0) ----
    in_mlp1<<<TB * HH / 256, 256>>>(x, Wi1, bi1, bufA);
    sgemm<<<dim3(HH/64, TB/64), 256>>>(TB, HH, HH, bufA, Wi2, nullptr, nullptr,
                                       bi2, nullptr, nullptr, bufB, 1);
    sgemm<<<dim3(HH/64, TB/64), 256>>>(TB, HH, HH, bufB, Wi3, nullptr, nullptr,
                                       bi3, nullptr, nullptr, bufC, 1);
    sgemm<<<dim3(G4/64, TB/64), 256>>>(TB, G4, HH, bufC, Wih0, nullptr, nullptr,
                                       bih0, bhh0, nullptr, A0, 0);

    zero_state<<<(4 * BB * HH) / 256, 256>>>(state);

    // ---- sequential phase: 128 timesteps, 2-layer LSTM ----
    for (int t = 0; t < TT; t++) {
        // gates0 = A0[t] + h0 @ Whh0^T
        sgemm<<<dim3(G4/64, BB/64), 256>>>(BB, G4, HH, h0, Whh0, nullptr, nullptr,
                                           nullptr, nullptr,
                                           A0 + (size_t)t * BB * G4, gates0, 0);
        lstm_cell<<<BB * HH / 256, 256>>>(gates0, c0, h0, nullptr);
        // gates1 = bih1 + bhh1 + h0 @ Wih1^T + h1 @ Whh1^T
        sgemm<<<dim3(G4/64, BB/64), 256>>>(BB, G4, HH, h0, Wih1, h1, Whh1,
                                           bih1, bhh1, nullptr, gates1, 0);
        // store relu(h1) directly into hs buffer (output MLP consumes relu(hs))
        lstm_cell<<<BB * HH / 256, 256>>>(gates1, c1, h1,
                                          bufA + (size_t)t * BB * HH);
    }

    // ---- output MLP ----
    sgemm<<<dim3(HH/64, TB/64), 256>>>(TB, HH, HH, bufA, Wo1, nullptr, nullptr,
                                       bo1, nullptr, nullptr, bufB, 1);
    sgemm<<<dim3(HH/64, TB/64), 256>>>(TB, HH, HH, bufB, Wo2, nullptr, nullptr,
                                       bo2, nullptr, nullptr, bufC, 1);
    out_mlp<<<(TB * 6 + 255) / 256, 256>>>(bufC, Wo3, bo3, out);
}

// round 2
// speedup vs baseline: 1.2633x; 1.2633x over previous
#include <cuda_runtime.h>
#include <math.h>

#define TT 128
#define BB 1024
#define HH 256
#define G4 1024
#define TB (TT*BB)

typedef unsigned long long u64;

// ---------------- scratch (allocation-free) ----------------
__device__ float g_bufA[(size_t)TB*HH];   // u / hs
__device__ float g_bufB[(size_t)TB*HH];
__device__ float g_bufC[(size_t)TB*HH];
__device__ float g_A0[(size_t)TB*G4];     // precomputed u@Wih0^T + bih0 + bhh0
__device__ float g_state[6*BB*HH];        // h0[2], h1[2], c0, c1
__device__ float g_bias1[G4];             // bih1 + bhh1

// ---------------- f32x2 helpers ----------------
__device__ __forceinline__ void fma2(u64 &d, u64 a, u64 b) {
    asm("fma.rn.f32x2 %0, %1, %2, %0;" : "+l"(d) : "l"(a), "l"(b));
}
__device__ __forceinline__ u64 dup2(float x) {
    u64 r; asm("mov.b64 %0, {%1, %1};" : "=l"(r) : "f"(x)); return r;
}
__device__ __forceinline__ float lo32(u64 v) {
    float f; asm("{ .reg .b32 t; mov.b64 {%0, t}, %1; }" : "=f"(f) : "l"(v)); return f;
}
__device__ __forceinline__ float hi32(u64 v) {
    float f; asm("{ .reg .b32 t; mov.b64 {t, %0}, %1; }" : "=f"(f) : "l"(v)); return f;
}

// ---------------- accurate-enough activations (err ~1e-6) ----------------
__device__ __forceinline__ float sigm_f(float x) {
    float e = __expf(-fabsf(x));
    float s = __fdividef(1.f, 1.f + e);        // sigmoid(|x|)
    return x >= 0.f ? s : 1.f - s;
}
__device__ __forceinline__ float tanh_f(float x) {
    float e = __expf(-2.f * fabsf(x));          // in (0,1]
    float r = __fdividef(1.f - e, 1.f + e);
    return copysignf(r, x);
}

// ---------------- misc small kernels ----------------
__global__ void zero6(float* s) {
    int i = blockIdx.x * blockDim.x + threadIdx.x;
    ((float4*)s)[i] = make_float4(0.f, 0.f, 0.f, 0.f);
}
__global__ void bias_comb(const float* a, const float* b, float* o) {
    int i = blockIdx.x * blockDim.x + threadIdx.x;
    o[i] = a[i] + b[i];
}
__global__ void in_mlp1(const float* __restrict__ x, const float* __restrict__ W,
                        const float* __restrict__ b, float* __restrict__ out) {
    int idx = blockIdx.x * blockDim.x + threadIdx.x;   // < TB*HH
    int m = idx >> 8, n = idx & 255;
    const float* xr = x + m * 6;
    const float* wr = W + n * 6;
    float s = b[n];
#pragma unroll
    for (int k = 0; k < 6; k++) s = fmaf(xr[k], wr[k], s);
    out[idx] = fmaxf(s, 0.f);
}

// ---------------- big-tile f32x2 SGEMM: C = act(A@B^T + bias1[+bias2]) ----------
// A:[M,K] B:[N,K] row-major. 128x128 tile, K-panel 8, 256 threads, 8x8 micro.
__global__ __launch_bounds__(256) void sgemm128(
    int M, int N, int K,
    const float* __restrict__ A, const float* __restrict__ B,
    const float* __restrict__ bias1, const float* __restrict__ bias2,
    float* __restrict__ C, int do_relu)
{
    __shared__ float As[8][132];
    __shared__ float Bs[8][132];
    int tid = threadIdx.x;
    int tx = tid & 15, ty = tid >> 4;
    int m0 = blockIdx.y << 7, n0 = blockIdx.x << 7;

    const float* Ald = A + (size_t)(m0 + (tid >> 1)) * K + (tid & 1) * 4;
    const float* Bld = B + (size_t)(n0 + (tid >> 1)) * K + (tid & 1) * 4;
    int kr = (tid & 1) * 4, mr = tid >> 1;

    u64 acc[4][8];
#pragma unroll
    for (int i = 0; i < 4; i++)
#pragma unroll
        for (int j = 0; j < 8; j++) acc[i][j] = 0ull;

    float4 ra = *(const float4*)Ald;
    float4 rb = *(const float4*)Bld;

    for (int k0 = 0; k0 < K; k0 += 8) {
        __syncthreads();
        As[kr+0][mr] = ra.x; As[kr+1][mr] = ra.y; As[kr+2][mr] = ra.z; As[kr+3][mr] = ra.w;
        Bs[kr+0][mr] = rb.x; Bs[kr+1][mr] = rb.y; Bs[kr+2][mr] = rb.z; Bs[kr+3][mr] = rb.w;
        __syncthreads();
        if (k0 + 8 < K) {
            ra = *(const float4*)(Ald + k0 + 8);
            rb = *(const float4*)(Bld + k0 + 8);
        }
#pragma unroll
        for (int k = 0; k < 8; k++) {
            ulonglong2 aL = *(const ulonglong2*)&As[k][ty * 4];
            ulonglong2 aH = *(const ulonglong2*)&As[k][ty * 4 + 64];
            float4 bL = *(const float4*)&Bs[k][tx * 4];
            float4 bH = *(const float4*)&Bs[k][tx * 4 + 64];
            u64 bd[8] = { dup2(bL.x), dup2(bL.y), dup2(bL.z), dup2(bL.w),
                          dup2(bH.x), dup2(bH.y), dup2(bH.z), dup2(bH.w) };
#pragma unroll
            for (int j = 0; j < 8; j++) {
                fma2(acc[0][j], aL.x, bd[j]);
                fma2(acc[1][j], aL.y, bd[j]);
                fma2(acc[2][j], aH.x, bd[j]);
                fma2(acc[3][j], aH.y, bd[j]);
            }
        }
    }

    // epilogue: quadrants (rq rows, cq cols)
#pragma unroll
    for (int cq = 0; cq < 2; cq++) {
        int cbase = n0 + tx * 4 + cq * 64;
        float4 bv = make_float4(0.f, 0.f, 0.f, 0.f);
        if (bias1) bv = *(const float4*)&bias1[cbase];
        if (bias2) {
            float4 b2 = *(const float4*)&bias2[cbase];
            bv.x += b2.x; bv.y += b2.y; bv.z += b2.z; bv.w += b2.w;
        }
#pragma unroll
        for (int rq = 0; rq < 2; rq++)
#pragma unroll
            for (int p = 0; p < 2; p++) {
                int rp = rq * 2 + p;
#pragma unroll
                for (int h = 0; h < 2; h++) {
                    int row = m0 + ty * 4 + rq * 64 + 2 * p + h;
                    float4 o;
                    o.x = (h ? hi32(acc[rp][cq*4+0]) : lo32(acc[rp][cq*4+0])) + bv.x;
                    o.y = (h ? hi32(acc[rp][cq*4+1]) : lo32(acc[rp][cq*4+1])) + bv.y;
                    o.z = (h ? hi32(acc[rp][cq*4+2]) : lo32(acc[rp][cq*4+2])) + bv.z;
                    o.w = (h ? hi32(acc[rp][cq*4+3]) : lo32(acc[rp][cq*4+3])) + bv.w;
                    if (do_relu) {
                        o.x = fmaxf(o.x, 0.f); o.y = fmaxf(o.y, 0.f);
                        o.z = fmaxf(o.z, 0.f); o.w = fmaxf(o.w, 0.f);
                    }
                    *(float4*)&C[(size_t)row * N + cbase] = o;
                }
            }
    }
}

// ---------------- fused LSTM step: gates GEMM + cell, one layer ----------------
// gates[b, g*256+j] = Apre_or_bias + hA@W^T (+ hA2@W2^T); then cell -> c,h,hs.
// Tile: 64 batch rows x 32 j (128 gate-cols, gate-interleaved). Grid (8, 16).
__global__ __launch_bounds__(256) void lstm_step(
    const float* __restrict__ hA,  const float* __restrict__ W,
    const float* __restrict__ hA2, const float* __restrict__ W2,
    const float* __restrict__ Apre,   // [BB, 1024] with biases, or null
    const float* __restrict__ bias,   // [1024] combined, or null
    float* __restrict__ cS, float* __restrict__ hOut, float* __restrict__ hsOut)
{
    __shared__ float As[8][68];
    __shared__ float Bs[8][132];
    int tid = threadIdx.x;
    int tx = tid & 31, ty = tid >> 5;
    int jb = blockIdx.x << 5, m0 = blockIdx.y << 6;

    u64 acc[4][4];
#pragma unroll
    for (int i = 0; i < 4; i++)
#pragma unroll
        for (int j = 0; j < 4; j++) acc[i][j] = 0ull;

    int br = tid >> 1;                       // 0..127: logical col = j*4+g
    int wrow = (br & 3) * 256 + jb + (br >> 2);
    int kr = (tid & 1) * 4;

    int npass = hA2 ? 2 : 1;
    for (int pass = 0; pass < npass; pass++) {
        const float* Ap = pass ? hA2 : hA;
        const float* Wp = pass ? W2  : W;
        const float* Bld = Wp + (size_t)wrow * HH + kr;
        const float* Ald = Ap + (size_t)(m0 + (tid >> 1)) * HH + kr;

        float4 rb = *(const float4*)Bld;
        float4 ra;
        if (tid < 128) ra = *(const float4*)Ald;

        for (int k0 = 0; k0 < HH; k0 += 8) {
            __syncthreads();
            Bs[kr+0][br] = rb.x; Bs[kr+1][br] = rb.y; Bs[kr+2][br] = rb.z; Bs[kr+3][br] = rb.w;
            if (tid < 128) {
                int amr = tid >> 1;
                As[kr+0][amr] = ra.x; As[kr+1][amr] = ra.y;
                As[kr+2][amr] = ra.z; As[kr+3][amr] = ra.w;
            }
            __syncthreads();
            if (k0 + 8 < HH) {
                rb = *(const float4*)(Bld + k0 + 8);
                if (tid < 128) ra = *(const float4*)(Ald + k0 + 8);
            }
#pragma unroll
            for (int k = 0; k < 8; k++) {
                ulonglong2 aL = *(const ulonglong2*)&As[k][ty * 8];
                ulonglong2 aH = *(const ulonglong2*)&As[k][ty * 8 + 4];
                float4 bv = *(const float4*)&Bs[k][tx * 4];
                u64 b0 = dup2(bv.x), b1 = dup2(bv.y), b2 = dup2(bv.z), b3 = dup2(bv.w);
                fma2(acc[0][0], aL.x, b0); fma2(acc[0][1], aL.x, b1);
                fma2(acc[0][2], aL.x, b2); fma2(acc[0][3], aL.x, b3);
                fma2(acc[1][0], aL.y, b0); fma2(acc[1][1], aL.y, b1);
                fma2(acc[1][2], aL.y, b2); fma2(acc[1][3], aL.y, b3);
                fma2(acc[2][0], aH.x, b0); fma2(acc[2][1], aH.x, b1);
                fma2(acc[2][2], aH.x, b2); fma2(acc[2][3], aH.x, b3);
                fma2(acc[3][0], aH.y, b0); fma2(acc[3][1], aH.y, b1);
                fma2(acc[3][2], aH.y, b2); fma2(acc[3][3], aH.y, b3);
            }
        }
    }

    // epilogue: cell. thread owns j = jb+tx, rows ty*8 + rp*2 + h
    int j = jb + tx;
#pragma unroll
    for (int rp = 0; rp < 4; rp++)
#pragma unroll
        for (int h = 0; h < 2; h++) {
            int row = m0 + ty * 8 + rp * 2 + h;
            float gi = h ? hi32(acc[rp][0]) : lo32(acc[rp][0]);
            float gf = h ? hi32(acc[rp][1]) : lo32(acc[rp][1]);
            float gg = h ? hi32(acc[rp][2]) : lo32(acc[rp][2]);
            float go = h ? hi32(acc[rp][3]) : lo32(acc[rp][3]);
            if (Apre) {
                const float* ap = Apre + (size_t)row * G4 + j;
                gi += ap[0]; gf += ap[256]; gg += ap[512]; go += ap[768];
            } else {
                gi += bias[j]; gf += bias[256 + j]; gg += bias[512 + j]; go += bias[768 + j];
            }
            int sidx = row * HH + j;
            float c2 = sigm_f(gf) * cS[sidx] + sigm_f(gi) * tanh_f(gg);
            float h2 = sigm_f(go) * tanh_f(c2);
            cS[sidx] = c2;
            hOut[sidx] = h2;
            if (hsOut) hsOut[sidx] = fmaxf(h2, 0.f);
        }
}

// ---------------- output final layer: warp per row, 6 outputs ----------------
__global__ void out_mlp_warp(const float* __restrict__ Y, const float* __restrict__ W,
                             const float* __restrict__ b, float* __restrict__ out) {
    int warp = (blockIdx.x * blockDim.x + threadIdx.x) >> 5;   // row m
    int lane = threadIdx.x & 31;
    const float* yr = Y + (size_t)warp * HH;
    float y[8];
#pragma unroll
    for (int i = 0; i < 8; i++) y[i] = yr[lane + 32 * i];
#pragma unroll
    for (int n = 0; n < 6; n++) {
        const float* wr = W + n * HH;
        float s = 0.f;
#pragma unroll
        for (int i = 0; i < 8; i++) s = fmaf(y[i], wr[lane + 32 * i], s);
#pragma unroll
        for (int off = 16; off; off >>= 1) s += __shfl_xor_sync(0xffffffffu, s, off);
        if (lane == 0) out[(size_t)warp * 6 + n] = s + b[n];
    }
}

// ---------------- launch ----------------
extern "C" void kernel_launch(void* const* d_in, const int* in_sizes, int n_in,
                              void* d_out, int out_size) {
    const float* x    = (const float*)d_in[0];
    const float* Wi1  = (const float*)d_in[1];
    const float* bi1  = (const float*)d_in[2];
    const float* Wi2  = (const float*)d_in[3];
    const float* bi2  = (const float*)d_in[4];
    const float* Wi3  = (const float*)d_in[5];
    const float* bi3  = (const float*)d_in[6];
    const float* Wih0 = (const float*)d_in[7];
    const float* Whh0 = (const float*)d_in[8];
    const float* bih0 = (const float*)d_in[9];
    const float* bhh0 = (const float*)d_in[10];
    const float* Wih1 = (const float*)d_in[11];
    const float* Whh1 = (const float*)d_in[12];
    const float* bih1 = (const float*)d_in[13];
    const float* bhh1 = (const float*)d_in[14];
    const float* Wo1  = (const float*)d_in[15];
    const float* bo1  = (const float*)d_in[16];
    const float* Wo2  = (const float*)d_in[17];
    const float* bo2  = (const float*)d_in[18];
    const float* Wo3  = (const float*)d_in[19];
    const float* bo3  = (const float*)d_in[20];
    float* out = (float*)d_out;

    float *bufA, *bufB, *bufC, *A0, *state, *bias1;
    cudaGetSymbolAddress((void**)&bufA, g_bufA);
    cudaGetSymbolAddress((void**)&bufB, g_bufB);
    cudaGetSymbolAddress((void**)&bufC, g_bufC);
    cudaGetSymbolAddress((void**)&A0, g_A0);
    cudaGetSymbolAddress((void**)&state, g_state);
    cudaGetSymbolAddress((void**)&bias1, g_bias1);

    float* h0[2] = { state,              state +     BB * HH };
    float* h1[2] = { state + 2 * BB * HH, state + 3 * BB * HH };
    float* c0 = state + 4 * BB * HH;
    float* c1 = state + 5 * BB * HH;

    // ---- parallel phase ----
    in_mlp1<<<TB * HH / 256, 256>>>(x, Wi1, bi1, bufA);
    sgemm128<<<dim3(2, TB / 128), 256>>>(TB, HH, HH, bufA, Wi2, bi2, nullptr, bufB, 1);
    sgemm128<<<dim3(2, TB / 128), 256>>>(TB, HH, HH, bufB, Wi3, bi3, nullptr, bufC, 1);
    sgemm128<<<dim3(8, TB / 128), 256>>>(TB, G4, HH, bufC, Wih0, bih0, bhh0, A0, 0);

    zero6<<<(6 * BB * HH / 4) / 256, 256>>>(state);
    bias_comb<<<G4 / 256, 256>>>(bih1, bhh1, bias1);

    // ---- sequential phase: 128 steps x 2 fused kernels ----
    for (int t = 0; t < TT; t++) {
        int pi = t & 1, po = (t + 1) & 1;
        lstm_step<<<dim3(8, 16), 256>>>(h0[pi], Whh0, nullptr, nullptr,
                                        A0 + (size_t)t * BB * G4, nullptr,
                                        c0, h0[po], nullptr);
        lstm_step<<<dim3(8, 16), 256>>>(h0[po], Wih1, h1[pi], Whh1,
                                        nullptr, bias1,
                                        c1, h1[po], bufA + (size_t)t * BB * HH);
    }

    // ---- output MLP ----
    sgemm128<<<dim3(2, TB / 128), 256>>>(TB, HH, HH, bufA, Wo1, bo1, nullptr, bufB, 1);
    sgemm128<<<dim3(2, TB / 128), 256>>>(TB, HH, HH, bufB, Wo2, bo2, nullptr, bufC, 1);
    out_mlp_warp<<<TB / 8, 256>>>(bufC, Wo3, bo3, out);
}

// round 4
// speedup vs baseline: 2.2842x; 1.8082x over previous
#include <cuda_runtime.h>
#include <math.h>
#include <cstdint>

#define TT 128
#define BB 1024
#define HH 256
#define G4 1024
#define TB (TT*BB)

typedef unsigned long long u64;

// ---------------- scratch (allocation-free) ----------------
__device__ float g_bufA[(size_t)TB*HH];
__device__ float g_bufB[(size_t)TB*HH];
__device__ float g_bufC[(size_t)TB*HH];
__device__ float g_A0[(size_t)TB*G4];     // u@Wih0^T + bih0 + bhh0 (fp32)
__device__ float g_state[6*BB*HH];        // h0[2], h1[2], c0, c1
__device__ float g_bias1[G4];             // bih1 + bhh1

// ---------------- f32x2 helpers (parallel-phase SGEMM) ----------------
__device__ __forceinline__ void fma2(u64 &d, u64 a, u64 b) {
    asm("fma.rn.f32x2 %0, %1, %2, %0;" : "+l"(d) : "l"(a), "l"(b));
}
__device__ __forceinline__ u64 dup2(float x) {
    u64 r; asm("mov.b64 %0, {%1, %1};" : "=l"(r) : "f"(x)); return r;
}
__device__ __forceinline__ float lo32(u64 v) {
    float f; asm("{ .reg .b32 t; mov.b64 {%0, t}, %1; }" : "=f"(f) : "l"(v)); return f;
}
__device__ __forceinline__ float hi32(u64 v) {
    float f; asm("{ .reg .b32 t; mov.b64 {t, %0}, %1; }" : "=f"(f) : "l"(v)); return f;
}

// ---------------- misc helpers ----------------
__device__ __forceinline__ uint32_t tf32r(float x) {
    uint32_t r; asm("cvt.rna.tf32.f32 %0, %1;" : "=r"(r) : "f"(x)); return r;
}
__device__ __forceinline__ float tanhfast(float x) {
    float r; asm("tanh.approx.f32 %0, %1;" : "=f"(r) : "f"(x)); return r;
}
__device__ __forceinline__ float sigfast(float x) {
    return fmaf(tanhfast(0.5f * x), 0.5f, 0.5f);
}
__device__ __forceinline__ void mma_tf32(float* d, const uint32_t* a, const uint32_t* b) {
    asm volatile(
        "mma.sync.aligned.m16n8k8.row.col.f32.tf32.tf32.f32 "
        "{%0,%1,%2,%3}, {%4,%5,%6,%7}, {%8,%9}, {%0,%1,%2,%3};"
        : "+f"(d[0]), "+f"(d[1]), "+f"(d[2]), "+f"(d[3])
        : "r"(a[0]), "r"(a[1]), "r"(a[2]), "r"(a[3]), "r"(b[0]), "r"(b[1]));
}

// ---------------- misc small kernels ----------------
__global__ void zero6(float* s) {
    int i = blockIdx.x * blockDim.x + threadIdx.x;
    ((float4*)s)[i] = make_float4(0.f, 0.f, 0.f, 0.f);
}
__global__ void bias_comb(const float* a, const float* b, float* o) {
    int i = blockIdx.x * blockDim.x + threadIdx.x;
    o[i] = a[i] + b[i];
}
__global__ void in_mlp1(const float* __restrict__ x, const float* __restrict__ W,
                        const float* __restrict__ b, float* __restrict__ out) {
    int idx = blockIdx.x * blockDim.x + threadIdx.x;
    int m = idx >> 8, n = idx & 255;
    const float* xr = x + m * 6;
    const float* wr = W + n * 6;
    float s = b[n];
#pragma unroll
    for (int k = 0; k < 6; k++) s = fmaf(xr[k], wr[k], s);
    out[idx] = fmaxf(s, 0.f);
}

// ---------------- big-tile f32x2 SGEMM (parallel phase) ----------------
__global__ __launch_bounds__(256) void sgemm128(
    int M, int N, int K,
    const float* __restrict__ A, const float* __restrict__ B,
    const float* __restrict__ bias1, const float* __restrict__ bias2,
    float* __restrict__ C, int do_relu)
{
    __shared__ float As[8][132];
    __shared__ float Bs[8][132];
    int tid = threadIdx.x;
    int tx = tid & 15, ty = tid >> 4;
    int m0 = blockIdx.y << 7, n0 = blockIdx.x << 7;

    const float* Ald = A + (size_t)(m0 + (tid >> 1)) * K + (tid & 1) * 4;
    const float* Bld = B + (size_t)(n0 + (tid >> 1)) * K + (tid & 1) * 4;
    int kr = (tid & 1) * 4, mr = tid >> 1;

    u64 acc[4][8];
#pragma unroll
    for (int i = 0; i < 4; i++)
#pragma unroll
        for (int j = 0; j < 8; j++) acc[i][j] = 0ull;

    float4 ra = *(const float4*)Ald;
    float4 rb = *(const float4*)Bld;

    for (int k0 = 0; k0 < K; k0 += 8) {
        __syncthreads();
        As[kr+0][mr] = ra.x; As[kr+1][mr] = ra.y; As[kr+2][mr] = ra.z; As[kr+3][mr] = ra.w;
        Bs[kr+0][mr] = rb.x; Bs[kr+1][mr] = rb.y; Bs[kr+2][mr] = rb.z; Bs[kr+3][mr] = rb.w;
        __syncthreads();
        if (k0 + 8 < K) {
            ra = *(const float4*)(Ald + k0 + 8);
            rb = *(const float4*)(Bld + k0 + 8);
        }
#pragma unroll
        for (int k = 0; k < 8; k++) {
            ulonglong2 aL = *(const ulonglong2*)&As[k][ty * 4];
            ulonglong2 aH = *(const ulonglong2*)&As[k][ty * 4 + 64];
            float4 bL = *(const float4*)&Bs[k][tx * 4];
            float4 bH = *(const float4*)&Bs[k][tx * 4 + 64];
            u64 bd[8] = { dup2(bL.x), dup2(bL.y), dup2(bL.z), dup2(bL.w),
                          dup2(bH.x), dup2(bH.y), dup2(bH.z), dup2(bH.w) };
#pragma unroll
            for (int j = 0; j < 8; j++) {
                fma2(acc[0][j], aL.x, bd[j]);
                fma2(acc[1][j], aL.y, bd[j]);
                fma2(acc[2][j], aH.x, bd[j]);
                fma2(acc[3][j], aH.y, bd[j]);
            }
        }
    }

#pragma unroll
    for (int cq = 0; cq < 2; cq++) {
        int cbase = n0 + tx * 4 + cq * 64;
        float4 bv = make_float4(0.f, 0.f, 0.f, 0.f);
        if (bias1) bv = *(const float4*)&bias1[cbase];
        if (bias2) {
            float4 b2 = *(const float4*)&bias2[cbase];
            bv.x += b2.x; bv.y += b2.y; bv.z += b2.z; bv.w += b2.w;
        }
#pragma unroll
        for (int rq = 0; rq < 2; rq++)
#pragma unroll
            for (int p = 0; p < 2; p++) {
                int rp = rq * 2 + p;
#pragma unroll
                for (int h = 0; h < 2; h++) {
                    int row = m0 + ty * 4 + rq * 64 + 2 * p + h;
                    float4 o;
                    o.x = (h ? hi32(acc[rp][cq*4+0]) : lo32(acc[rp][cq*4+0])) + bv.x;
                    o.y = (h ? hi32(acc[rp][cq*4+1]) : lo32(acc[rp][cq*4+1])) + bv.y;
                    o.z = (h ? hi32(acc[rp][cq*4+2]) : lo32(acc[rp][cq*4+2])) + bv.z;
                    o.w = (h ? hi32(acc[rp][cq*4+3]) : lo32(acc[rp][cq*4+3])) + bv.w;
                    if (do_relu) {
                        o.x = fmaxf(o.x, 0.f); o.y = fmaxf(o.y, 0.f);
                        o.z = fmaxf(o.z, 0.f); o.w = fmaxf(o.w, 0.f);
                    }
                    *(float4*)&C[(size_t)row * N + cbase] = o;
                }
            }
    }
}

// ---------------- tf32 mma.sync fused LSTM step ----------------
// gates = Apre_or_bias + hA@W^T [+ hA2@W2^T], then cell fused in registers.
// CTA tile: M=64 batch x 32 j (4 gates in separate mma n-tiles).
// 8 warps (2m x 4j). Grid (8, 16). Dynamic smem: double-buffered A(64x64) B(128x64).
#define KCH 64
#define APAD 68
#define AS_F (64*APAD)          // floats per A buffer
#define BS_F (128*APAD)         // floats per B buffer
#define SMEM_LSTM ((2*AS_F + 2*BS_F)*4)

__global__ __launch_bounds__(256, 1) void lstm_mma(
    const float* __restrict__ hA,  const float* __restrict__ W,
    const float* __restrict__ hA2, const float* __restrict__ W2,
    const float* __restrict__ Apre, const float* __restrict__ bias,
    float* __restrict__ cS, float* __restrict__ hOut, float* __restrict__ hsOut)
{
    extern __shared__ float sdyn[];
    int tid = threadIdx.x;
    int lane = tid & 31, wid = tid >> 5;
    int wm = wid >> 2, wn = wid & 3;          // warp grid 2m x 4j
    int gid = lane >> 2, tidg = lane & 3;
    int jb = blockIdx.x << 5;                 // j block (32 j's)
    int m0 = blockIdx.y << 6;                 // batch block (64 rows)

    float acc[2][4][4];
#pragma unroll
    for (int mt = 0; mt < 2; mt++)
#pragma unroll
        for (int g = 0; g < 4; g++)
#pragma unroll
            for (int q = 0; q < 4; q++) acc[mt][g][q] = 0.f;

    int C = hA2 ? 8 : 4;

    // staging indices
    int arow = tid >> 4, akq = (tid & 15) << 2;    // A: 4 iters cover 64x64
    int brow0 = tid >> 4;                          // B: 8 iters cover 128x64

    float4 ra[4], rb[8];

    // ---- prologue: load + store chunk 0 ----
    {
        const float* As = hA;
        const float* Ws = W;
#pragma unroll
        for (int i = 0; i < 4; i++)
            ra[i] = *(const float4*)(As + (size_t)(m0 + arow + i * 16) * HH + akq);
#pragma unroll
        for (int i = 0; i < 8; i++) {
            int row = brow0 + i * 16;
            int Wrow = (row >> 5) * 256 + jb + (row & 31);
            rb[i] = *(const float4*)(Ws + (size_t)Wrow * HH + akq);
        }
#pragma unroll
        for (int i = 0; i < 4; i++) {
            uint4 v = make_uint4(tf32r(ra[i].x), tf32r(ra[i].y), tf32r(ra[i].z), tf32r(ra[i].w));
            *(uint4*)&sdyn[(arow + i * 16) * APAD + akq] = v;
        }
#pragma unroll
        for (int i = 0; i < 8; i++) {
            uint4 v = make_uint4(tf32r(rb[i].x), tf32r(rb[i].y), tf32r(rb[i].z), tf32r(rb[i].w));
            *(uint4*)&sdyn[2 * AS_F + (brow0 + i * 16) * APAD + akq] = v;
        }
    }

    for (int c = 0; c < C; c++) {
        __syncthreads();
        int buf = c & 1;
        // issue gmem loads for next chunk
        if (c + 1 < C) {
            const float* As = (c + 1 < 4) ? hA : hA2;
            const float* Ws = (c + 1 < 4) ? W  : W2;
            int kb = ((c + 1) & 3) * KCH;
#pragma unroll
            for (int i = 0; i < 4; i++)
                ra[i] = *(const float4*)(As + (size_t)(m0 + arow + i * 16) * HH + kb + akq);
#pragma unroll
            for (int i = 0; i < 8; i++) {
                int row = brow0 + i * 16;
                int Wrow = (row >> 5) * 256 + jb + (row & 31);
                rb[i] = *(const float4*)(Ws + (size_t)Wrow * HH + kb + akq);
            }
        }
        // compute on current buffer
        const float* Ab = sdyn + buf * AS_F;
        const float* Bb = sdyn + 2 * AS_F + buf * BS_F;
#pragma unroll
        for (int kk = 0; kk < 8; kk++) {
            int k = kk * 8;
            uint32_t af[2][4];
#pragma unroll
            for (int mt = 0; mt < 2; mt++) {
                int rbase = wm * 32 + mt * 16;
                af[mt][0] = __float_as_uint(Ab[(rbase + gid) * APAD + k + tidg]);
                af[mt][1] = __float_as_uint(Ab[(rbase + gid + 8) * APAD + k + tidg]);
                af[mt][2] = __float_as_uint(Ab[(rbase + gid) * APAD + k + tidg + 4]);
                af[mt][3] = __float_as_uint(Ab[(rbase + gid + 8) * APAD + k + tidg + 4]);
            }
            uint32_t bf[4][2];
#pragma unroll
            for (int g = 0; g < 4; g++) {
                int n = g * 32 + wn * 8 + gid;
                bf[g][0] = __float_as_uint(Bb[n * APAD + k + tidg]);
                bf[g][1] = __float_as_uint(Bb[n * APAD + k + tidg + 4]);
            }
#pragma unroll
            for (int mt = 0; mt < 2; mt++)
#pragma unroll
                for (int g = 0; g < 4; g++)
                    mma_tf32(acc[mt][g], af[mt], bf[g]);
        }
        // store next chunk into the other buffer
        if (c + 1 < C) {
            int nbuf = (c + 1) & 1;
#pragma unroll
            for (int i = 0; i < 4; i++) {
                uint4 v = make_uint4(tf32r(ra[i].x), tf32r(ra[i].y), tf32r(ra[i].z), tf32r(ra[i].w));
                *(uint4*)&sdyn[nbuf * AS_F + (arow + i * 16) * APAD + akq] = v;
            }
#pragma unroll
            for (int i = 0; i < 8; i++) {
                uint4 v = make_uint4(tf32r(rb[i].x), tf32r(rb[i].y), tf32r(rb[i].z), tf32r(rb[i].w));
                *(uint4*)&sdyn[2 * AS_F + nbuf * BS_F + (brow0 + i * 16) * APAD + akq] = v;
            }
        }
    }

    // ---- epilogue: fused LSTM cell. thread owns 4 rows x 2 j ----
    int j2 = jb + wn * 8 + tidg * 2;     // two j's: j2, j2+1
#pragma unroll
    for (int mt = 0; mt < 2; mt++)
#pragma unroll
        for (int rh = 0; rh < 2; rh++) {
            int row = m0 + wm * 32 + mt * 16 + rh * 8 + gid;
            float2 aI, aF, aG, aO;
            if (Apre) {
                const float* ap = Apre + (size_t)row * G4 + j2;
                aI = *(const float2*)(ap);
                aF = *(const float2*)(ap + 256);
                aG = *(const float2*)(ap + 512);
                aO = *(const float2*)(ap + 768);
            } else {
                aI = *(const float2*)(bias + j2);
                aF = *(const float2*)(bias + 256 + j2);
                aG = *(const float2*)(bias + 512 + j2);
                aO = *(const float2*)(bias + 768 + j2);
            }
            float2 cc = *(const float2*)(cS + (size_t)row * HH + j2);
            float2 ho, co, hs;
#pragma unroll
            for (int jj = 0; jj < 2; jj++) {
                float gi = acc[mt][0][rh * 2 + jj] + (jj ? aI.y : aI.x);
                float gf = acc[mt][1][rh * 2 + jj] + (jj ? aF.y : aF.x);
                float gG = acc[mt][2][rh * 2 + jj] + (jj ? aG.y : aG.x);
                float go = acc[mt][3][rh * 2 + jj] + (jj ? aO.y : aO.x);
                float cprev = jj ? cc.y : cc.x;
                float c2 = sigfast(gf) * cprev + sigfast(gi) * tanhfast(gG);
                float h2 = sigfast(go) * tanhfast(c2);
                if (jj) { co.y = c2; ho.y = h2; hs.y = fmaxf(h2, 0.f); }
                else    { co.x = c2; ho.x = h2; hs.x = fmaxf(h2, 0.f); }
            }
            *(float2*)(cS   + (size_t)row * HH + j2) = co;
            *(float2*)(hOut + (size_t)row * HH + j2) = ho;
            if (hsOut) *(float2*)(hsOut + (size_t)row * HH + j2) = hs;
        }
}

// ---------------- output final layer ----------------
__global__ void out_mlp_warp(const float* __restrict__ Y, const float* __restrict__ W,
                             const float* __restrict__ b, float* __restrict__ out) {
    int warp = (blockIdx.x * blockDim.x + threadIdx.x) >> 5;
    int lane = threadIdx.x & 31;
    const float* yr = Y + (size_t)warp * HH;
    float y[8];
#pragma unroll
    for (int i = 0; i < 8; i++) y[i] = yr[lane + 32 * i];
#pragma unroll
    for (int n = 0; n < 6; n++) {
        const float* wr = W + n * HH;
        float s = 0.f;
#pragma unroll
        for (int i = 0; i < 8; i++) s = fmaf(y[i], wr[lane + 32 * i], s);
#pragma unroll
        for (int off = 16; off; off >>= 1) s += __shfl_xor_sync(0xffffffffu, s, off);
        if (lane == 0) out[(size_t)warp * 6 + n] = s + b[n];
    }
}

// ---------------- launch ----------------
extern "C" void kernel_launch(void* const* d_in, const int* in_sizes, int n_in,
                              void* d_out, int out_size) {
    const float* x    = (const float*)d_in[0];
    const float* Wi1  = (const float*)d_in[1];
    const float* bi1  = (const float*)d_in[2];
    const float* Wi2  = (const float*)d_in[3];
    const float* bi2  = (const float*)d_in[4];
    const float* Wi3  = (const float*)d_in[5];
    const float* bi3  = (const float*)d_in[6];
    const float* Wih0 = (const float*)d_in[7];
    const float* Whh0 = (const float*)d_in[8];
    const float* bih0 = (const float*)d_in[9];
    const float* bhh0 = (const float*)d_in[10];
    const float* Wih1 = (const float*)d_in[11];
    const float* Whh1 = (const float*)d_in[12];
    const float* bih1 = (const float*)d_in[13];
    const float* bhh1 = (const float*)d_in[14];
    const float* Wo1  = (const float*)d_in[15];
    const float* bo1  = (const float*)d_in[16];
    const float* Wo2  = (const float*)d_in[17];
    const float* bo2  = (const float*)d_in[18];
    const float* Wo3  = (const float*)d_in[19];
    const float* bo3  = (const float*)d_in[20];
    float* out = (float*)d_out;

    float *bufA, *bufB, *bufC, *A0, *state, *bias1;
    cudaGetSymbolAddress((void**)&bufA, g_bufA);
    cudaGetSymbolAddress((void**)&bufB, g_bufB);
    cudaGetSymbolAddress((void**)&bufC, g_bufC);
    cudaGetSymbolAddress((void**)&A0, g_A0);
    cudaGetSymbolAddress((void**)&state, g_state);
    cudaGetSymbolAddress((void**)&bias1, g_bias1);

    cudaFuncSetAttribute(lstm_mma, cudaFuncAttributeMaxDynamicSharedMemorySize, SMEM_LSTM);

    float* h0[2] = { state,               state +     BB * HH };
    float* h1[2] = { state + 2 * BB * HH, state + 3 * BB * HH };
    float* c0 = state + 4 * BB * HH;
    float* c1 = state + 5 * BB * HH;

    // ---- parallel phase (fp32) ----
    in_mlp1<<<TB * HH / 256, 256>>>(x, Wi1, bi1, bufA);
    sgemm128<<<dim3(2, TB / 128), 256>>>(TB, HH, HH, bufA, Wi2, bi2, nullptr, bufB, 1);
    sgemm128<<<dim3(2, TB / 128), 256>>>(TB, HH, HH, bufB, Wi3, bi3, nullptr, bufC, 1);
    sgemm128<<<dim3(8, TB / 128), 256>>>(TB, G4, HH, bufC, Wih0, bih0, bhh0, A0, 0);

    zero6<<<(6 * BB * HH / 4) / 256, 256>>>(state);
    bias_comb<<<G4 / 256, 256>>>(bih1, bhh1, bias1);

    // ---- sequential phase: tf32 HMMA, 2 fused kernels/step ----
    for (int t = 0; t < TT; t++) {
        int pi = t & 1, po = (t + 1) & 1;
        lstm_mma<<<dim3(8, 16), 256, SMEM_LSTM>>>(
            h0[pi], Whh0, nullptr, nullptr,
            A0 + (size_t)t * BB * G4, nullptr,
            c0, h0[po], nullptr);
        lstm_mma<<<dim3(8, 16), 256, SMEM_LSTM>>>(
            h0[po], Wih1, h1[pi], Whh1,
            nullptr, bias1,
            c1, h1[po], bufA + (size_t)t * BB * HH);
    }

    // ---- output MLP (fp32) ----
    sgemm128<<<dim3(2, TB / 128), 256>>>(TB, HH, HH, bufA, Wo1, bo1, nullptr, bufB, 1);
    sgemm128<<<dim3(2, TB / 128), 256>>>(TB, HH, HH, bufB, Wo2, bo2, nullptr, bufC, 1);
    out_mlp_warp<<<TB / 8, 256>>>(bufC, Wo3, bo3, out);
}

// round 8
// speedup vs baseline: 2.7782x; 1.2163x over previous
#include <cuda_runtime.h>
#include <math.h>
#include <cstdint>

#define TT 128
#define BB 1024
#define HH 256
#define G4 1024
#define TB (TT*BB)

typedef unsigned long long u64;

// ---------------- scratch (allocation-free) ----------------
__device__ float g_bufA[(size_t)TB*HH];
__device__ float g_bufB[(size_t)TB*HH];
__device__ float g_bufC[(size_t)TB*HH];
__device__ float g_A0[(size_t)TB*G4];     // u@Wih0^T + bih0 + bhh0
__device__ float g_state[6*BB*HH];        // h0[2], h1[2], c0, c1
__device__ float g_bias1[G4];             // bih1 + bhh1
__device__ float g_bias0[G4];             // bih0 + bhh0

// ---------------- helpers ----------------
__device__ __forceinline__ uint32_t tf32r(float x) {
    uint32_t r; asm("cvt.rna.tf32.f32 %0, %1;" : "=r"(r) : "f"(x)); return r;
}
__device__ __forceinline__ float tanhfast(float x) {
    float r; asm("tanh.approx.f32 %0, %1;" : "=f"(r) : "f"(x)); return r;
}
__device__ __forceinline__ float sigfast(float x) {
    return fmaf(tanhfast(0.5f * x), 0.5f, 0.5f);
}
__device__ __forceinline__ void mma_tf32(float* d, const uint32_t* a, const uint32_t* b) {
    asm volatile(
        "mma.sync.aligned.m16n8k8.row.col.f32.tf32.tf32.f32 "
        "{%0,%1,%2,%3}, {%4,%5,%6,%7}, {%8,%9}, {%0,%1,%2,%3};"
        : "+f"(d[0]), "+f"(d[1]), "+f"(d[2]), "+f"(d[3])
        : "r"(a[0]), "r"(a[1]), "r"(a[2]), "r"(a[3]), "r"(b[0]), "r"(b[1]));
}

// ---------------- small kernels ----------------
__global__ void zero6(float* s) {
    int i = blockIdx.x * blockDim.x + threadIdx.x;
    ((float4*)s)[i] = make_float4(0.f, 0.f, 0.f, 0.f);
}
__global__ void bias_comb(const float* a, const float* b, float* o) {
    int i = blockIdx.x * blockDim.x + threadIdx.x;
    o[i] = a[i] + b[i];
}
__global__ void in_mlp1(const float* __restrict__ x, const float* __restrict__ W,
                        const float* __restrict__ b, float* __restrict__ out) {
    int idx = blockIdx.x * blockDim.x + threadIdx.x;
    int m = idx >> 8, n = idx & 255;
    const float* xr = x + m * 6;
    const float* wr = W + n * 6;
    float s = b[n];
#pragma unroll
    for (int k = 0; k < 6; k++) s = fmaf(xr[k], wr[k], s);
    out[idx] = fmaxf(s, 0.f);
}

// ---------------- shared smem config for mma kernels ----------------
#define KCH 64
#define APAD 68
#define AS_F (64*APAD)
#define BS_F (128*APAD)
#define SMEM_MMA ((2*AS_F + 2*BS_F)*4)

// ---------------- generic tf32 mma GEMM: C = act(A@B^T + bias) ----------------
// CTA tile 64(m) x 128(n), K chunks of 64, double-buffered. Grid (N/128, M/64).
__global__ __launch_bounds__(256, 1) void gemm_mma(
    int N, int K,
    const float* __restrict__ A, const float* __restrict__ B,
    const float* __restrict__ bias, float* __restrict__ C, int do_relu)
{
    extern __shared__ float sdyn[];
    int tid = threadIdx.x;
    int lane = tid & 31, wid = tid >> 5;
    int wm = wid >> 2, wn = wid & 3;
    int gid = lane >> 2, tidg = lane & 3;
    int n0 = blockIdx.x << 7;
    int m0 = blockIdx.y << 6;

    float acc[2][4][4];
#pragma unroll
    for (int mt = 0; mt < 2; mt++)
#pragma unroll
        for (int g = 0; g < 4; g++)
#pragma unroll
            for (int q = 0; q < 4; q++) acc[mt][g][q] = 0.f;

    int CH = K >> 6;
    int arow = tid >> 4, akq = (tid & 15) << 2;
    float4 ra[4], rb[8];

    // prologue: chunk 0
#pragma unroll
    for (int i = 0; i < 4; i++)
        ra[i] = *(const float4*)(A + (size_t)(m0 + arow + i * 16) * K + akq);
#pragma unroll
    for (int i = 0; i < 8; i++)
        rb[i] = *(const float4*)(B + (size_t)(n0 + arow + i * 16) * K + akq);
#pragma unroll
    for (int i = 0; i < 4; i++) {
        uint4 v = make_uint4(tf32r(ra[i].x), tf32r(ra[i].y), tf32r(ra[i].z), tf32r(ra[i].w));
        *(uint4*)&sdyn[(arow + i * 16) * APAD + akq] = v;
    }
#pragma unroll
    for (int i = 0; i < 8; i++) {
        uint4 v = make_uint4(tf32r(rb[i].x), tf32r(rb[i].y), tf32r(rb[i].z), tf32r(rb[i].w));
        *(uint4*)&sdyn[2 * AS_F + (arow + i * 16) * APAD + akq] = v;
    }

    for (int c = 0; c < CH; c++) {
        __syncthreads();
        int buf = c & 1;
        if (c + 1 < CH) {
            int kb = (c + 1) << 6;
#pragma unroll
            for (int i = 0; i < 4; i++)
                ra[i] = *(const float4*)(A + (size_t)(m0 + arow + i * 16) * K + kb + akq);
#pragma unroll
            for (int i = 0; i < 8; i++)
                rb[i] = *(const float4*)(B + (size_t)(n0 + arow + i * 16) * K + kb + akq);
        }
        const float* Ab = sdyn + buf * AS_F;
        const float* Bb = sdyn + 2 * AS_F + buf * BS_F;
#pragma unroll
        for (int kk = 0; kk < 8; kk++) {
            int k = kk * 8;
            uint32_t af[2][4];
#pragma unroll
            for (int mt = 0; mt < 2; mt++) {
                int rbase = wm * 32 + mt * 16;
                af[mt][0] = __float_as_uint(Ab[(rbase + gid) * APAD + k + tidg]);
                af[mt][1] = __float_as_uint(Ab[(rbase + gid + 8) * APAD + k + tidg]);
                af[mt][2] = __float_as_uint(Ab[(rbase + gid) * APAD + k + tidg + 4]);
                af[mt][3] = __float_as_uint(Ab[(rbase + gid + 8) * APAD + k + tidg + 4]);
            }
            uint32_t bf[4][2];
#pragma unroll
            for (int g = 0; g < 4; g++) {
                int n = g * 32 + wn * 8 + gid;
                bf[g][0] = __float_as_uint(Bb[n * APAD + k + tidg]);
                bf[g][1] = __float_as_uint(Bb[n * APAD + k + tidg + 4]);
            }
#pragma unroll
            for (int mt = 0; mt < 2; mt++)
#pragma unroll
                for (int g = 0; g < 4; g++)
                    mma_tf32(acc[mt][g], af[mt], bf[g]);
        }
        if (c + 1 < CH) {
            int nbuf = (c + 1) & 1;
#pragma unroll
            for (int i = 0; i < 4; i++) {
                uint4 v = make_uint4(tf32r(ra[i].x), tf32r(ra[i].y), tf32r(ra[i].z), tf32r(ra[i].w));
                *(uint4*)&sdyn[nbuf * AS_F + (arow + i * 16) * APAD + akq] = v;
            }
#pragma unroll
            for (int i = 0; i < 8; i++) {
                uint4 v = make_uint4(tf32r(rb[i].x), tf32r(rb[i].y), tf32r(rb[i].z), tf32r(rb[i].w));
                *(uint4*)&sdyn[2 * AS_F + nbuf * BS_F + (arow + i * 16) * APAD + akq] = v;
            }
        }
    }

    // epilogue
#pragma unroll
    for (int g = 0; g < 4; g++) {
        int cb = n0 + g * 32 + wn * 8 + tidg * 2;
        float2 bv = *(const float2*)(bias + cb);
#pragma unroll
        for (int mt = 0; mt < 2; mt++)
#pragma unroll
            for (int rh = 0; rh < 2; rh++) {
                int row = m0 + wm * 32 + mt * 16 + rh * 8 + gid;
                float2 o;
                o.x = acc[mt][g][rh * 2 + 0] + bv.x;
                o.y = acc[mt][g][rh * 2 + 1] + bv.y;
                if (do_relu) { o.x = fmaxf(o.x, 0.f); o.y = fmaxf(o.y, 0.f); }
                *(float2*)&C[(size_t)row * N + cb] = o;
            }
    }
}

// ---------------- tf32 mma fused LSTM step (unchanged from R4) ----------------
__global__ __launch_bounds__(256, 1) void lstm_mma(
    const float* __restrict__ hA,  const float* __restrict__ W,
    const float* __restrict__ hA2, const float* __restrict__ W2,
    const float* __restrict__ Apre, const float* __restrict__ bias,
    float* __restrict__ cS, float* __restrict__ hOut, float* __restrict__ hsOut)
{
    extern __shared__ float sdyn[];
    int tid = threadIdx.x;
    int lane = tid & 31, wid = tid >> 5;
    int wm = wid >> 2, wn = wid & 3;
    int gid = lane >> 2, tidg = lane & 3;
    int jb = blockIdx.x << 5;
    int m0 = blockIdx.y << 6;

    float acc[2][4][4];
#pragma unroll
    for (int mt = 0; mt < 2; mt++)
#pragma unroll
        for (int g = 0; g < 4; g++)
#pragma unroll
            for (int q = 0; q < 4; q++) acc[mt][g][q] = 0.f;

    int C = hA2 ? 8 : 4;
    int arow = tid >> 4, akq = (tid & 15) << 2;
    int brow0 = tid >> 4;
    float4 ra[4], rb[8];

    {
        const float* As = hA;
        const float* Ws = W;
#pragma unroll
        for (int i = 0; i < 4; i++)
            ra[i] = *(const float4*)(As + (size_t)(m0 + arow + i * 16) * HH + akq);
#pragma unroll
        for (int i = 0; i < 8; i++) {
            int row = brow0 + i * 16;
            int Wrow = (row >> 5) * 256 + jb + (row & 31);
            rb[i] = *(const float4*)(Ws + (size_t)Wrow * HH + akq);
        }
#pragma unroll
        for (int i = 0; i < 4; i++) {
            uint4 v = make_uint4(tf32r(ra[i].x), tf32r(ra[i].y), tf32r(ra[i].z), tf32r(ra[i].w));
            *(uint4*)&sdyn[(arow + i * 16) * APAD + akq] = v;
        }
#pragma unroll
        for (int i = 0; i < 8; i++) {
            uint4 v = make_uint4(tf32r(rb[i].x), tf32r(rb[i].y), tf32r(rb[i].z), tf32r(rb[i].w));
            *(uint4*)&sdyn[2 * AS_F + (brow0 + i * 16) * APAD + akq] = v;
        }
    }

    for (int c = 0; c < C; c++) {
        __syncthreads();
        int buf = c & 1;
        if (c + 1 < C) {
            const float* As = (c + 1 < 4) ? hA : hA2;
            const float* Ws = (c + 1 < 4) ? W  : W2;
            int kb = ((c + 1) & 3) * KCH;
#pragma unroll
            for (int i = 0; i < 4; i++)
                ra[i] = *(const float4*)(As + (size_t)(m0 + arow + i * 16) * HH + kb + akq);
#pragma unroll
            for (int i = 0; i < 8; i++) {
                int row = brow0 + i * 16;
                int Wrow = (row >> 5) * 256 + jb + (row & 31);
                rb[i] = *(const float4*)(Ws + (size_t)Wrow * HH + kb + akq);
            }
        }
        const float* Ab = sdyn + buf * AS_F;
        const float* Bb = sdyn + 2 * AS_F + buf * BS_F;
#pragma unroll
        for (int kk = 0; kk < 8; kk++) {
            int k = kk * 8;
            uint32_t af[2][4];
#pragma unroll
            for (int mt = 0; mt < 2; mt++) {
                int rbase = wm * 32 + mt * 16;
                af[mt][0] = __float_as_uint(Ab[(rbase + gid) * APAD + k + tidg]);
                af[mt][1] = __float_as_uint(Ab[(rbase + gid + 8) * APAD + k + tidg]);
                af[mt][2] = __float_as_uint(Ab[(rbase + gid) * APAD + k + tidg + 4]);
                af[mt][3] = __float_as_uint(Ab[(rbase + gid + 8) * APAD + k + tidg + 4]);
            }
            uint32_t bf[4][2];
#pragma unroll
            for (int g = 0; g < 4; g++) {
                int n = g * 32 + wn * 8 + gid;
                bf[g][0] = __float_as_uint(Bb[n * APAD + k + tidg]);
                bf[g][1] = __float_as_uint(Bb[n * APAD + k + tidg + 4]);
            }
#pragma unroll
            for (int mt = 0; mt < 2; mt++)
#pragma unroll
                for (int g = 0; g < 4; g++)
                    mma_tf32(acc[mt][g], af[mt], bf[g]);
        }
        if (c + 1 < C) {
            int nbuf = (c + 1) & 1;
#pragma unroll
            for (int i = 0; i < 4; i++) {
                uint4 v = make_uint4(tf32r(ra[i].x), tf32r(ra[i].y), tf32r(ra[i].z), tf32r(ra[i].w));
                *(uint4*)&sdyn[nbuf * AS_F + (arow + i * 16) * APAD + akq] = v;
            }
#pragma unroll
            for (int i = 0; i < 8; i++) {
                uint4 v = make_uint4(tf32r(rb[i].x), tf32r(rb[i].y), tf32r(rb[i].z), tf32r(rb[i].w));
                *(uint4*)&sdyn[2 * AS_F + nbuf * BS_F + (brow0 + i * 16) * APAD + akq] = v;
            }
        }
    }

    int j2 = jb + wn * 8 + tidg * 2;
#pragma unroll
    for (int mt = 0; mt < 2; mt++)
#pragma unroll
        for (int rh = 0; rh < 2; rh++) {
            int row = m0 + wm * 32 + mt * 16 + rh * 8 + gid;
            float2 aI, aF, aG, aO;
            if (Apre) {
                const float* ap = Apre + (size_t)row * G4 + j2;
                aI = *(const float2*)(ap);
                aF = *(const float2*)(ap + 256);
                aG = *(const float2*)(ap + 512);
                aO = *(const float2*)(ap + 768);
            } else {
                aI = *(const float2*)(bias + j2);
                aF = *(const float2*)(bias + 256 + j2);
                aG = *(const float2*)(bias + 512 + j2);
                aO = *(const float2*)(bias + 768 + j2);
            }
            float2 cc = *(const float2*)(cS + (size_t)row * HH + j2);
            float2 ho, co, hs;
#pragma unroll
            for (int jj = 0; jj < 2; jj++) {
                float gi = acc[mt][0][rh * 2 + jj] + (jj ? aI.y : aI.x);
                float gf = acc[mt][1][rh * 2 + jj] + (jj ? aF.y : aF.x);
                float gG = acc[mt][2][rh * 2 + jj] + (jj ? aG.y : aG.x);
                float go = acc[mt][3][rh * 2 + jj] + (jj ? aO.y : aO.x);
                float cprev = jj ? cc.y : cc.x;
                float c2 = sigfast(gf) * cprev + sigfast(gi) * tanhfast(gG);
                float h2 = sigfast(go) * tanhfast(c2);
                if (jj) { co.y = c2; ho.y = h2; hs.y = fmaxf(h2, 0.f); }
                else    { co.x = c2; ho.x = h2; hs.x = fmaxf(h2, 0.f); }
            }
            *(float2*)(cS   + (size_t)row * HH + j2) = co;
            *(float2*)(hOut + (size_t)row * HH + j2) = ho;
            if (hsOut) *(float2*)(hsOut + (size_t)row * HH + j2) = hs;
        }
}

// ---------------- output final layer ----------------
__global__ void out_mlp_warp(const float* __restrict__ Y, const float* __restrict__ W,
                             const float* __restrict__ b, float* __restrict__ out) {
    int warp = (blockIdx.x * blockDim.x + threadIdx.x) >> 5;
    int lane = threadIdx.x & 31;
    const float* yr = Y + (size_t)warp * HH;
    float y[8];
#pragma unroll
    for (int i = 0; i < 8; i++) y[i] = yr[lane + 32 * i];
#pragma unroll
    for (int n = 0; n < 6; n++) {
        const float* wr = W + n * HH;
        float s = 0.f;
#pragma unroll
        for (int i = 0; i < 8; i++) s = fmaf(y[i], wr[lane + 32 * i], s);
#pragma unroll
        for (int off = 16; off; off >>= 1) s += __shfl_xor_sync(0xffffffffu, s, off);
        if (lane == 0) out[(size_t)warp * 6 + n] = s + b[n];
    }
}

// ---------------- launch ----------------
extern "C" void kernel_launch(void* const* d_in, const int* in_sizes, int n_in,
                              void* d_out, int out_size) {
    const float* x    = (const float*)d_in[0];
    const float* Wi1  = (const float*)d_in[1];
    const float* bi1  = (const float*)d_in[2];
    const float* Wi2  = (const float*)d_in[3];
    const float* bi2  = (const float*)d_in[4];
    const float* Wi3  = (const float*)d_in[5];
    const float* bi3  = (const float*)d_in[6];
    const float* Wih0 = (const float*)d_in[7];
    const float* Whh0 = (const float*)d_in[8];
    const float* bih0 = (const float*)d_in[9];
    const float* bhh0 = (const float*)d_in[10];
    const float* Wih1 = (const float*)d_in[11];
    const float* Whh1 = (const float*)d_in[12];
    const float* bih1 = (const float*)d_in[13];
    const float* bhh1 = (const float*)d_in[14];
    const float* Wo1  = (const float*)d_in[15];
    const float* bo1  = (const float*)d_in[16];
    const float* Wo2  = (const float*)d_in[17];
    const float* bo2  = (const float*)d_in[18];
    const float* Wo3  = (const float*)d_in[19];
    const float* bo3  = (const float*)d_in[20];
    float* out = (float*)d_out;

    float *bufA, *bufB, *bufC, *A0, *state, *bias1, *bias0;
    cudaGetSymbolAddress((void**)&bufA, g_bufA);
    cudaGetSymbolAddress((void**)&bufB, g_bufB);
    cudaGetSymbolAddress((void**)&bufC, g_bufC);
    cudaGetSymbolAddress((void**)&A0, g_A0);
    cudaGetSymbolAddress((void**)&state, g_state);
    cudaGetSymbolAddress((void**)&bias1, g_bias1);
    cudaGetSymbolAddress((void**)&bias0, g_bias0);

    cudaFuncSetAttribute(lstm_mma, cudaFuncAttributeMaxDynamicSharedMemorySize, SMEM_MMA);
    cudaFuncSetAttribute(gemm_mma, cudaFuncAttributeMaxDynamicSharedMemorySize, SMEM_MMA);

    float* h0[2] = { state,               state +     BB * HH };
    float* h1[2] = { state + 2 * BB * HH, state + 3 * BB * HH };
    float* c0 = state + 4 * BB * HH;
    float* c1 = state + 5 * BB * HH;

    // ---- parallel phase (tf32 mma) ----
    in_mlp1<<<TB * HH / 256, 256>>>(x, Wi1, bi1, bufA);
    gemm_mma<<<dim3(2, TB / 64), 256, SMEM_MMA>>>(HH, HH, bufA, Wi2, bi2, bufB, 1);
    gemm_mma<<<dim3(2, TB / 64), 256, SMEM_MMA>>>(HH, HH, bufB, Wi3, bi3, bufC, 1);
    bias_comb<<<G4 / 256, 256>>>(bih0, bhh0, bias0);
    gemm_mma<<<dim3(8, TB / 64), 256, SMEM_MMA>>>(G4, HH, bufC, Wih0, bias0, A0, 0);

    zero6<<<(6 * BB * HH / 4) / 256, 256>>>(state);
    bias_comb<<<G4 / 256, 256>>>(bih1, bhh1, bias1);

    // ---- sequential phase: tf32 HMMA, 2 fused kernels/step ----
    for (int t = 0; t < TT; t++) {
        int pi = t & 1, po = (t + 1) & 1;
        lstm_mma<<<dim3(8, 16), 256, SMEM_MMA>>>(
            h0[pi], Whh0, nullptr, nullptr,
            A0 + (size_t)t * BB * G4, nullptr,
            c0, h0[po], nullptr);
        lstm_mma<<<dim3(8, 16), 256, SMEM_MMA>>>(
            h0[po], Wih1, h1[pi], Whh1,
            nullptr, bias1,
            c1, h1[po], bufA + (size_t)t * BB * HH);
    }

    // ---- output MLP (tf32 mma) ----
    gemm_mma<<<dim3(2, TB / 64), 256, SMEM_MMA>>>(HH, HH, bufA, Wo1, bo1, bufB, 1);
    gemm_mma<<<dim3(2, TB / 64), 256, SMEM_MMA>>>(HH, HH, bufB, Wo2, bo2, bufC, 1);
    out_mlp_warp<<<TB / 8, 256>>>(bufC, Wo3, bo3, out);
}